// round 5
// baseline (speedup 1.0000x reference)
#include <cuda_runtime.h>
#include <math.h>

#define BB 16
#define MM 32
#define WW 256
#define NN 65536      // 256*256
#define CC 27
#define T1 256
#define QBLK 2048     // 4 blocks per (b,m) plane
#define QELEM 16384   // elements per quarter-plane

// ---- scratch (unique writer per element -> no data races) ----
__device__ __align__(16) unsigned char g_sem8[BB * NN];
__device__ float g_histPart[QBLK * 32];   // 27 used, padded to 32
__device__ float g_blkI[QBLK];
__device__ float g_blkU[QBLK];
__device__ float g_blkD[QBLK];
__device__ unsigned int g_count = 0;

// ---------------------------------------------------------------------------
// Pack: sem int32 -> uint8 (1 MiB; L2-resident for the 32x reuse in hist).
// ---------------------------------------------------------------------------
__global__ __launch_bounds__(256) void pack_kernel(const int* __restrict__ sem) {
    int i = blockIdx.x * 256 + threadIdx.x;     // BB*NN/4 uchar4
    int4 v = ((const int4*)sem)[i];
    uchar4 o;
    o.x = (unsigned char)v.x; o.y = (unsigned char)v.y;
    o.z = (unsigned char)v.z; o.w = (unsigned char)v.w;
    ((uchar4*)g_sem8)[i] = o;
}

// ---------------------------------------------------------------------------
// Fused kernel: 2048 blocks, 256 threads.
//  plane   = blk>>2 (the (b,m) pair), quarter = blk&3  -> histogram partials
//  slice   = 512 px of the boundary/depth losses (blk&127 within batch blk>>7)
//  Last finished block combines everything and writes the 4 scalars.
// ---------------------------------------------------------------------------
__global__ __launch_bounds__(T1) void fused_kernel(const int* __restrict__ sem,
                                                   const float* __restrict__ masks,
                                                   const float* __restrict__ depth,
                                                   float* __restrict__ out) {
    __shared__ float s_hist[CC * T1];          // 27,648 B; conflict-free RMW
    __shared__ float s_red[T1 / 32][CC];
    __shared__ float rI[T1 / 32], rU[T1 / 32], rD[T1 / 32];
    __shared__ bool  s_isLast;

    const int blk     = blockIdx.x;
    const int plane   = blk >> 2;              // (b,m)
    const int quarter = blk & 3;
    const int b       = blk >> 7;              // batch (same for both parts)
    const int tid     = threadIdx.x;
    const int lane    = tid & 31;
    const int wid     = tid >> 5;

    float* my = s_hist + tid;
#pragma unroll
    for (int c = 0; c < CC; c++) my[c * T1] = 0.f;

    // ---- Part 1: pixel losses on 512-px slice ----
    const int4*   semv = (const int4*)sem + ((size_t)b << 14);
    const float4* m0v  = (const float4*)(masks + (size_t)b * MM * NN);
    const float4* dv   = (const float4*)depth + ((size_t)b << 14);
    const int*    semS = sem + ((size_t)b << 16);
    const float*  m0S  = masks + (size_t)b * MM * NN;
    const float*  dS   = depth + ((size_t)b << 16);

    float inter = 0.f, uni = 0.f, contrib = 0.f;
    if (tid < 128) {
        int n  = ((blk & 127) << 9) + (tid << 2);   // slice base + group
        int gi = n >> 2;
        int y  = n >> 8, x = n & 255;
        int4   s4  = semv[gi];
        float4 m4  = m0v[gi];
        float4 d4  = dv[gi];
        int giu = (y > 0) ? gi - 64 : gi;
        int4   s4u = semv[giu];
        float4 m4u = m0v[giu];
        float4 d4u = dv[giu];
        int sl0; float ml0, dl0;
        if (x > 0) { sl0 = semS[n - 1]; ml0 = m0S[n - 1]; dl0 = dS[n - 1]; }
        else       { sl0 = s4.x;        ml0 = m4.x;       dl0 = d4.x; }

        int   s[4]  = {s4.x, s4.y, s4.z, s4.w};
        int   sl[4] = {sl0, s4.x, s4.y, s4.z};
        int   su[4] = {s4u.x, s4u.y, s4u.z, s4u.w};
        float m[4]  = {m4.x, m4.y, m4.z, m4.w};
        float ml[4] = {ml0, m4.x, m4.y, m4.z};
        float mu[4] = {m4u.x, m4u.y, m4u.z, m4u.w};
        float d[4]  = {d4.x, d4.y, d4.z, d4.w};
        float dl[4] = {dl0, d4.x, d4.y, d4.z};
        float du[4] = {d4u.x, d4u.y, d4u.z, d4u.w};
#pragma unroll
        for (int e = 0; e < 4; e++) {
            float semb  = (s[e] != sl[e] || s[e] != su[e]) ? 1.f : 0.f;
            float instb = (fabsf(m[e] - ml[e]) > 0.3f ||
                           fabsf(m[e] - mu[e]) > 0.3f) ? 1.f : 0.f;
            inter += semb * instb;
            uni   += fmaxf(semb, instb);
            float gx = d[e] - dl[e], gy = d[e] - du[e];
            float ss = gx * gx + gy * gy;
            float db = sqrtf(fmaxf(ss, 1e-24f));
            float dbc = fminf(db, 2.f);
            contrib += (1.f + 3.f * dbc) * (1.f - semb) * dbc;
        }
    }
#pragma unroll
    for (int o = 16; o > 0; o >>= 1) {
        inter   += __shfl_down_sync(0xffffffffu, inter,   o);
        uni     += __shfl_down_sync(0xffffffffu, uni,     o);
        contrib += __shfl_down_sync(0xffffffffu, contrib, o);
    }
    if (lane == 0) { rI[wid] = inter; rU[wid] = uni; rD[wid] = contrib; }

    // ---- Part 2: histogram over quarter-plane (16 float4 groups/thread) ----
    const float4* mp = (const float4*)(masks + (size_t)plane * NN) + quarter * (QELEM / 4);
    const uchar4* sp = (const uchar4*)(g_sem8 + ((size_t)b << 16)) + quarter * (QELEM / 4);
#pragma unroll 4
    for (int j = 0; j < 8; j++) {
        int i0 = tid + j * 512;
        float4 v0 = mp[i0];
        float4 v1 = mp[i0 + 256];
        uchar4 c0 = sp[i0];
        uchar4 c1 = sp[i0 + 256];
        my[(int)c0.x * T1] += v0.x;
        my[(int)c0.y * T1] += v0.y;
        my[(int)c0.z * T1] += v0.z;
        my[(int)c0.w * T1] += v0.w;
        my[(int)c1.x * T1] += v1.x;
        my[(int)c1.y * T1] += v1.y;
        my[(int)c1.z * T1] += v1.z;
        my[(int)c1.w * T1] += v1.w;
    }
    __syncwarp();

    float h[CC];
#pragma unroll
    for (int c = 0; c < CC; c++) h[c] = my[c * T1];
#pragma unroll
    for (int o = 16; o > 0; o >>= 1) {
#pragma unroll
        for (int c = 0; c < CC; c++) h[c] += __shfl_xor_sync(0xffffffffu, h[c], o);
    }
    if (lane == 0) {
#pragma unroll
        for (int c = 0; c < CC; c++) s_red[wid][c] = h[c];
    }
    __syncthreads();

    if (wid == 0) {
        if (lane < CC) {
            float t = 0.f;
#pragma unroll
            for (int w = 0; w < T1 / 32; w++) t += s_red[w][lane];
            g_histPart[blk * 32 + lane] = t;
        }
    } else if (wid == 1 && lane == 0) {
        float I = 0.f, U = 0.f, D = 0.f;
#pragma unroll
        for (int w = 0; w < T1 / 32; w++) { I += rI[w]; U += rU[w]; D += rD[w]; }
        g_blkI[blk] = I;
        g_blkU[blk] = U;
        g_blkD[blk] = D;
    }

    // ---- Last-block finalize ----
    __threadfence();
    __syncthreads();
    if (tid == 0) {
        unsigned int v = atomicAdd(&g_count, 1u);
        s_isLast = (v == (unsigned int)(gridDim.x - 1));
    }
    __syncthreads();
    if (!s_isLast) return;

    // entropy: thread t handles (b,m) pairs t and t+256
    float esum = 0.f;
#pragma unroll
    for (int k = 0; k < 2; k++) {
        int p = tid + k * 256;
        float hh[CC];
        float msum = 1e-6f;
#pragma unroll
        for (int c = 0; c < CC; c++) {
            float v = g_histPart[(p * 4 + 0) * 32 + c]
                    + g_histPart[(p * 4 + 1) * 32 + c]
                    + g_histPart[(p * 4 + 2) * 32 + c]
                    + g_histPart[(p * 4 + 3) * 32 + c];
            hh[c] = v;
            msum += v;
        }
        float inv = 1.f / msum;
#pragma unroll
        for (int c = 0; c < CC; c++) {
            float pr = hh[c] * inv;
            pr = fminf(fmaxf(pr, 1e-7f), 1.0f);
            if (pr > 1e-6f) esum -= pr * __logf(pr + 1e-10f);
        }
    }
    // boundary: warp w handles batches w and w+8 (128 blocks each, 4 per lane)
    float rsum = 0.f, dsum = 0.f;
#pragma unroll
    for (int k = 0; k < 2; k++) {
        int bb = wid + k * 8;
        float I = 0.f, U = 0.f, D = 0.f;
#pragma unroll
        for (int r = 0; r < 4; r++) {
            int idx = bb * 128 + lane * 4 + r;
            I += g_blkI[idx];
            U += g_blkU[idx];
            D += g_blkD[idx];
        }
#pragma unroll
        for (int o = 16; o > 0; o >>= 1) {
            I += __shfl_xor_sync(0xffffffffu, I, o);
            U += __shfl_xor_sync(0xffffffffu, U, o);
            D += __shfl_xor_sync(0xffffffffu, D, o);
        }
        rsum += I / (U + 1e-8f);
        dsum += D;
    }
#pragma unroll
    for (int o = 16; o > 0; o >>= 1) esum += __shfl_xor_sync(0xffffffffu, esum, o);

    __shared__ float sE[8], sR[8], sD2[8];
    if (lane == 0) { sE[wid] = esum; sR[wid] = rsum; sD2[wid] = dsum; }
    __syncthreads();
    if (tid == 0) {
        float etot = 0.f, rtot = 0.f, dtot = 0.f;
#pragma unroll
        for (int w = 0; w < 8; w++) { etot += sE[w]; rtot += sR[w]; dtot += sD2[w]; }
        float lu = etot / (512.f + 1e-8f);
        float lb = 1.f - rtot * (1.f / 16.f);
        float ld = dtot * (1.f / ((float)BB * (float)NN));
        out[0] = lu;
        out[1] = lb;
        out[2] = ld;
        out[3] = 0.3f * lu + 0.2f * lb + 0.2f * ld;
        g_count = 0;                           // reset for next graph replay
    }
}

// ---------------------------------------------------------------------------
extern "C" void kernel_launch(void* const* d_in, const int* in_sizes, int n_in,
                              void* d_out, int out_size) {
    const int*   sem   = (const int*)d_in[0];
    const float* masks = (const float*)d_in[1];
    const float* depth = (const float*)d_in[2];
    float* out = (float*)d_out;

    pack_kernel<<<(BB * NN / 4) / 256, 256>>>(sem);              // 1024 blocks
    fused_kernel<<<QBLK, T1>>>(sem, masks, depth, out);          // 2048 blocks
}

// round 11
// speedup vs baseline: 1.9929x; 1.9929x over previous
#include <cuda_runtime.h>
#include <math.h>

#define BB 16
#define MM 32
#define WW 256
#define NN 65536      // 256*256
#define CC 27
#define T1 256
#define NBLK 1024     // 2 blocks per (b,m) plane
#define HELEM 32768   // elements per half-plane

// ---- scratch (unique writer per element -> no data races) ----
__device__ __align__(16) unsigned char g_sem8[BB * NN];
__device__ float g_histPart[NBLK * 32];   // 27 used, padded to 32
__device__ float g_blkI[NBLK];
__device__ float g_blkU[NBLK];
__device__ float g_blkD[NBLK];
__device__ unsigned int g_count = 0;

// ---------------------------------------------------------------------------
// Pack: sem int32 -> uint8 (1 MiB; L2-resident for the 32x reuse in hist).
// ---------------------------------------------------------------------------
__global__ __launch_bounds__(256) void pack_kernel(const int* __restrict__ sem) {
    int i = blockIdx.x * 256 + threadIdx.x;     // BB*NN/4 uchar4
    int4 v = ((const int4*)sem)[i];
    uchar4 o;
    o.x = (unsigned char)v.x; o.y = (unsigned char)v.y;
    o.z = (unsigned char)v.z; o.w = (unsigned char)v.w;
    ((uchar4*)g_sem8)[i] = o;
}

// ---------------------------------------------------------------------------
// Fused kernel: 1024 blocks, 256 threads.
//  hist : plane = blk>>1, half = blk&1 (32K elements).
//         Per-thread private column-major smem bins (bank = tid%32 -> every
//         RMW conflict-free). Epilogue: warp w reduces classes 4w..4w+3 via
//         strided LDS + single-value shuffles (NO register-array butterfly).
//  pixel: 1024-px slice of the boundary/depth losses (blk&63 in batch blk>>6).
//  Last finished block combines partials and writes the 4 scalars.
// ---------------------------------------------------------------------------
__global__ __launch_bounds__(T1) void fused_kernel(const int* __restrict__ sem,
                                                   const float* __restrict__ masks,
                                                   const float* __restrict__ depth,
                                                   float* __restrict__ out) {
    __shared__ float s_hist[CC * T1];          // 27,648 B; conflict-free RMW
    __shared__ float rI[T1 / 32], rU[T1 / 32], rD[T1 / 32];
    __shared__ bool  s_isLast;

    const int blk   = blockIdx.x;
    const int plane = blk >> 1;                // (b,m)
    const int half  = blk & 1;
    const int b     = blk >> 6;                // batch
    const int tid   = threadIdx.x;
    const int lane  = tid & 31;
    const int wid   = tid >> 5;

    float* my = s_hist + tid;
#pragma unroll
    for (int c = 0; c < CC; c++) my[c * T1] = 0.f;

    // ---- Part 1: pixel losses on a 1024-px slice ----
    const int4*   semv = (const int4*)sem + ((size_t)b << 14);
    const float4* m0v  = (const float4*)(masks + (size_t)b * MM * NN);
    const float4* dv   = (const float4*)depth + ((size_t)b << 14);
    const int*    semS = sem + ((size_t)b << 16);
    const float*  m0S  = masks + (size_t)b * MM * NN;
    const float*  dS   = depth + ((size_t)b << 16);

    float inter = 0.f, uni = 0.f, contrib = 0.f;
    {
        int gi = ((blk & 63) << 8) + tid;      // float4-group index in batch
        int n  = gi << 2;
        int y  = n >> 8, x = n & 255;
        int4   s4  = semv[gi];
        float4 m4  = m0v[gi];
        float4 d4  = dv[gi];
        int giu = (y > 0) ? gi - 64 : gi;      // row above (replicate at y==0)
        int4   s4u = semv[giu];
        float4 m4u = m0v[giu];
        float4 d4u = dv[giu];
        int sl0; float ml0, dl0;
        if (x > 0) { sl0 = semS[n - 1]; ml0 = m0S[n - 1]; dl0 = dS[n - 1]; }
        else       { sl0 = s4.x;        ml0 = m4.x;       dl0 = d4.x; }

        int   s[4]  = {s4.x, s4.y, s4.z, s4.w};
        int   sl[4] = {sl0, s4.x, s4.y, s4.z};
        int   su[4] = {s4u.x, s4u.y, s4u.z, s4u.w};
        float m[4]  = {m4.x, m4.y, m4.z, m4.w};
        float ml[4] = {ml0, m4.x, m4.y, m4.z};
        float mu[4] = {m4u.x, m4u.y, m4u.z, m4u.w};
        float d[4]  = {d4.x, d4.y, d4.z, d4.w};
        float dl[4] = {dl0, d4.x, d4.y, d4.z};
        float du[4] = {d4u.x, d4u.y, d4u.z, d4u.w};
#pragma unroll
        for (int e = 0; e < 4; e++) {
            float semb  = (s[e] != sl[e] || s[e] != su[e]) ? 1.f : 0.f;
            float instb = (fabsf(m[e] - ml[e]) > 0.3f ||
                           fabsf(m[e] - mu[e]) > 0.3f) ? 1.f : 0.f;
            inter += semb * instb;
            uni   += fmaxf(semb, instb);
            float gx = d[e] - dl[e], gy = d[e] - du[e];
            float ss = gx * gx + gy * gy;
            float db = sqrtf(fmaxf(ss, 1e-24f));
            float dbc = fminf(db, 2.f);
            contrib += (1.f + 3.f * dbc) * (1.f - semb) * dbc;
        }
    }
#pragma unroll
    for (int o = 16; o > 0; o >>= 1) {
        inter   += __shfl_down_sync(0xffffffffu, inter,   o);
        uni     += __shfl_down_sync(0xffffffffu, uni,     o);
        contrib += __shfl_down_sync(0xffffffffu, contrib, o);
    }
    if (lane == 0) { rI[wid] = inter; rU[wid] = uni; rD[wid] = contrib; }

    // ---- Part 2: histogram over half-plane (32 float4 groups/thread) ----
    const float4* mp = (const float4*)(masks + (size_t)plane * NN) + half * (HELEM / 4);
    const uchar4* sp = (const uchar4*)(g_sem8 + ((size_t)b << 16)) + half * (HELEM / 4);
#pragma unroll 4
    for (int j = 0; j < 16; j++) {
        int i0 = tid + j * 512;
        float4 v0 = mp[i0];
        float4 v1 = mp[i0 + 256];
        uchar4 c0 = sp[i0];
        uchar4 c1 = sp[i0 + 256];
        my[(int)c0.x * T1] += v0.x;
        my[(int)c0.y * T1] += v0.y;
        my[(int)c0.z * T1] += v0.z;
        my[(int)c0.w * T1] += v0.w;
        my[(int)c1.x * T1] += v1.x;
        my[(int)c1.y * T1] += v1.y;
        my[(int)c1.z * T1] += v1.z;
        my[(int)c1.w * T1] += v1.w;
    }
    __syncthreads();                           // all columns written

    // cheap epilogue: warp w reduces classes 4w..4w+3 (strided LDS, no spills)
#pragma unroll
    for (int k = 0; k < 4; k++) {
        int c = wid * 4 + k;
        if (c < CC) {
            const float* row = s_hist + c * T1;
            float v = 0.f;
#pragma unroll
            for (int g = 0; g < 8; g++) v += row[lane + g * 32];
#pragma unroll
            for (int o = 16; o > 0; o >>= 1) v += __shfl_xor_sync(0xffffffffu, v, o);
            if (lane == 0) g_histPart[blk * 32 + c] = v;
        }
    }
    if (wid == 1 && lane == 0) {
        float I = 0.f, U = 0.f, D = 0.f;
#pragma unroll
        for (int w = 0; w < T1 / 32; w++) { I += rI[w]; U += rU[w]; D += rD[w]; }
        g_blkI[blk] = I;
        g_blkU[blk] = U;
        g_blkD[blk] = D;
    }

    // ---- Last-block finalize ----
    __threadfence();
    __syncthreads();
    if (tid == 0) {
        unsigned int v = atomicAdd(&g_count, 1u);
        s_isLast = (v == (unsigned int)(gridDim.x - 1));
    }
    __syncthreads();
    if (!s_isLast) return;

    // entropy: thread t handles (b,m) planes t and t+256
    float esum = 0.f;
#pragma unroll
    for (int k = 0; k < 2; k++) {
        int p = tid + k * 256;
        float msum = 1e-6f;
        float hh[CC];
#pragma unroll
        for (int c = 0; c < CC; c++) {
            float v = g_histPart[(p * 2 + 0) * 32 + c]
                    + g_histPart[(p * 2 + 1) * 32 + c];
            hh[c] = v;
            msum += v;
        }
        float inv = 1.f / msum;
#pragma unroll
        for (int c = 0; c < CC; c++) {
            float pr = hh[c] * inv;
            pr = fminf(fmaxf(pr, 1e-7f), 1.0f);
            if (pr > 1e-6f) esum -= pr * __logf(pr + 1e-10f);
        }
    }
    // boundary: warp w handles batches w and w+8 (64 blocks each, 2 per lane)
    float rsum = 0.f, dsum = 0.f;
#pragma unroll
    for (int k = 0; k < 2; k++) {
        int bb = wid + k * 8;
        float I = 0.f, U = 0.f, D = 0.f;
#pragma unroll
        for (int r = 0; r < 2; r++) {
            int idx = bb * 64 + lane * 2 + r;
            I += g_blkI[idx];
            U += g_blkU[idx];
            D += g_blkD[idx];
        }
#pragma unroll
        for (int o = 16; o > 0; o >>= 1) {
            I += __shfl_xor_sync(0xffffffffu, I, o);
            U += __shfl_xor_sync(0xffffffffu, U, o);
            D += __shfl_xor_sync(0xffffffffu, D, o);
        }
        rsum += I / (U + 1e-8f);
        dsum += D;
    }
#pragma unroll
    for (int o = 16; o > 0; o >>= 1) esum += __shfl_xor_sync(0xffffffffu, esum, o);

    __shared__ float sE[8], sR[8], sD2[8];
    if (lane == 0) { sE[wid] = esum; sR[wid] = rsum; sD2[wid] = dsum; }
    __syncthreads();
    if (tid == 0) {
        float etot = 0.f, rtot = 0.f, dtot = 0.f;
#pragma unroll
        for (int w = 0; w < 8; w++) { etot += sE[w]; rtot += sR[w]; dtot += sD2[w]; }
        float lu = etot / (512.f + 1e-8f);
        float lb = 1.f - rtot * (1.f / 16.f);
        float ld = dtot * (1.f / ((float)BB * (float)NN));
        out[0] = lu;
        out[1] = lb;
        out[2] = ld;
        out[3] = 0.3f * lu + 0.2f * lb + 0.2f * ld;
        g_count = 0;                           // reset for next graph replay
    }
}

// ---------------------------------------------------------------------------
extern "C" void kernel_launch(void* const* d_in, const int* in_sizes, int n_in,
                              void* d_out, int out_size) {
    const int*   sem   = (const int*)d_in[0];
    const float* masks = (const float*)d_in[1];
    const float* depth = (const float*)d_in[2];
    float* out = (float*)d_out;

    pack_kernel<<<(BB * NN / 4) / 256, 256>>>(sem);              // 1024 blocks
    fused_kernel<<<NBLK, T1>>>(sem, masks, depth, out);          // 1024 blocks
}

// round 14
// speedup vs baseline: 2.3478x; 1.1781x over previous
#include <cuda_runtime.h>
#include <math.h>

#define BB 16
#define MM 32
#define NN 65536      // 256*256
#define CC 27
#define TT 128        // threads per block
#define NBLK 1024     // 2 blocks per (b,m) plane
#define HGRP 8192     // float4 groups per half-plane

// ---- scratch (unique writer per element; counters self-reset for graph replay) ----
__device__ float g_histPart[NBLK * 32];     // per-block 27-bin partials (padded 32)
__device__ float g_entArr[BB * MM];         // per-plane entropy
__device__ float g_blkI[NBLK];
__device__ float g_blkU[NBLK];
__device__ float g_blkD[NBLK];
__device__ unsigned int g_pcount[BB * MM];  // per-plane arrival counter
__device__ unsigned int g_count = 0;        // global arrival counter

// ---------------------------------------------------------------------------
// Single fused kernel: 1024 blocks x 128 threads.
//  pixel: 1024-px slice of boundary/depth losses (blk&63 within batch blk>>6)
//  hist : half-plane (32K elems) masked histogram into TWO separately-declared
//         per-thread-column smem arrays (sA/sB) -> ptxas-provable no-alias ->
//         two independent RMW chains per thread (2x ILP on the LDS->FADD->STS
//         dependency that binds this loop). bank = tid%32: conflict-free.
//  plane-tail: second block of each plane computes that plane's entropy
//  global-tail: last of 1024 blocks reduces everything, writes 4 scalars
// ---------------------------------------------------------------------------
__global__ __launch_bounds__(TT) void fused_kernel(const int* __restrict__ sem,
                                                   const float* __restrict__ masks,
                                                   const float* __restrict__ depth,
                                                   float* __restrict__ out) {
    __shared__ float sA[CC * TT];           // 13,824 B
    __shared__ float sB[CC * TT];           // 13,824 B  (distinct object: no alias)
    __shared__ float rI[4], rU[4], rD[4];
    __shared__ float sE[4], sR[4], sD2[4];
    __shared__ bool  s_doEnt, s_isLast;

    const int blk   = blockIdx.x;
    const int plane = blk >> 1;             // (b,m)
    const int half  = blk & 1;
    const int b     = blk >> 6;             // batch
    const int tid   = threadIdx.x;
    const int lane  = tid & 31;
    const int wid   = tid >> 5;             // 4 warps

    float* aT = sA + tid;                   // stream A bins: aT[c<<7]
    float* bT = sB + tid;                   // stream B bins: bT[c<<7]
#pragma unroll
    for (int c = 0; c < CC; c++) { aT[c << 7] = 0.f; bT[c << 7] = 0.f; }

    // ---- Part 1: pixel losses, 256 float4-groups per block (2 per thread) ----
    const int4*   semv = (const int4*)sem + ((size_t)b << 14);
    const float4* m0v  = (const float4*)(masks + (size_t)b * MM * NN);
    const float4* dv   = (const float4*)depth + ((size_t)b << 14);
    const int*    semS = sem + ((size_t)b << 16);
    const float*  m0S  = masks + (size_t)b * MM * NN;
    const float*  dS   = depth + ((size_t)b << 16);

    float inter = 0.f, uni = 0.f, contrib = 0.f;
#pragma unroll
    for (int q = 0; q < 2; q++) {
        int gi = ((blk & 63) << 8) + (q << 7) + tid;   // group index in batch
        int n  = gi << 2;
        int y  = n >> 8, x = n & 255;
        int4   s4  = semv[gi];
        float4 m4  = m0v[gi];
        float4 d4  = dv[gi];
        int giu = (y > 0) ? gi - 64 : gi;   // row above (replicate at y==0)
        int4   s4u = semv[giu];
        float4 m4u = m0v[giu];
        float4 d4u = dv[giu];
        int sl0; float ml0, dl0;
        if (x > 0) { sl0 = semS[n - 1]; ml0 = m0S[n - 1]; dl0 = dS[n - 1]; }
        else       { sl0 = s4.x;        ml0 = m4.x;       dl0 = d4.x; }

        int   s[4]  = {s4.x, s4.y, s4.z, s4.w};
        int   sl[4] = {sl0, s4.x, s4.y, s4.z};
        int   su[4] = {s4u.x, s4u.y, s4u.z, s4u.w};
        float m[4]  = {m4.x, m4.y, m4.z, m4.w};
        float ml[4] = {ml0, m4.x, m4.y, m4.z};
        float mu[4] = {m4u.x, m4u.y, m4u.z, m4u.w};
        float d[4]  = {d4.x, d4.y, d4.z, d4.w};
        float dl[4] = {dl0, d4.x, d4.y, d4.z};
        float du[4] = {d4u.x, d4u.y, d4u.z, d4u.w};
#pragma unroll
        for (int e = 0; e < 4; e++) {
            float semb  = (s[e] != sl[e] || s[e] != su[e]) ? 1.f : 0.f;
            float instb = (fabsf(m[e] - ml[e]) > 0.3f ||
                           fabsf(m[e] - mu[e]) > 0.3f) ? 1.f : 0.f;
            inter += semb * instb;
            uni   += fmaxf(semb, instb);
            float gx = d[e] - dl[e], gy = d[e] - du[e];
            float ss = gx * gx + gy * gy;
            float db = sqrtf(fmaxf(ss, 1e-24f));
            float dbc = fminf(db, 2.f);
            contrib += (1.f + 3.f * dbc) * (1.f - semb) * dbc;
        }
    }
#pragma unroll
    for (int o = 16; o > 0; o >>= 1) {
        inter   += __shfl_down_sync(0xffffffffu, inter,   o);
        uni     += __shfl_down_sync(0xffffffffu, uni,     o);
        contrib += __shfl_down_sync(0xffffffffu, contrib, o);
    }
    if (lane == 0) { rI[wid] = inter; rU[wid] = uni; rD[wid] = contrib; }

    // ---- Part 2: histogram over half-plane, dual-stream RMW ----
    const float4* mp = (const float4*)(masks + (size_t)plane * NN) + half * HGRP;
    const int4*   sp = semv + half * HGRP;
#pragma unroll 4
    for (int j = 0; j < 32; j++) {
        int i0 = tid + (j << 8);
        float4 v0 = mp[i0];
        float4 v1 = mp[i0 + 128];
        int4   c0 = sp[i0];
        int4   c1 = sp[i0 + 128];
        aT[c0.x << 7] += v0.x;      // stream A
        bT[c0.y << 7] += v0.y;      // stream B (independent of A's STS)
        aT[c0.z << 7] += v0.z;
        bT[c0.w << 7] += v0.w;
        aT[c1.x << 7] += v1.x;
        bT[c1.y << 7] += v1.y;
        aT[c1.z << 7] += v1.z;
        bT[c1.w << 7] += v1.w;
    }
    __syncthreads();

    // spill-free epilogue: warp w reduces classes {w, w+4, ..., w+24}
#pragma unroll
    for (int k = 0; k < 7; k++) {
        int c = wid + (k << 2);
        if (c < CC) {
            const float* ra = sA + (c << 7);
            const float* rb = sB + (c << 7);
            float v = 0.f;
#pragma unroll
            for (int g = 0; g < 4; g++) v += ra[lane + (g << 5)] + rb[lane + (g << 5)];
#pragma unroll
            for (int o = 16; o > 0; o >>= 1) v += __shfl_xor_sync(0xffffffffu, v, o);
            if (lane == 0) g_histPart[blk * 32 + c] = v;
        }
    }
    if (tid == 0) {
        g_blkI[blk] = rI[0] + rI[1] + rI[2] + rI[3];
        g_blkU[blk] = rU[0] + rU[1] + rU[2] + rU[3];
        g_blkD[blk] = rD[0] + rD[1] + rD[2] + rD[3];
    }

    // ---- plane tail: second-arriving block computes this plane's entropy ----
    __threadfence();
    __syncthreads();
    if (tid == 0) {
        unsigned int v = atomicAdd(&g_pcount[plane], 1u);
        s_doEnt = (v == 1u);
    }
    __syncthreads();
    if (s_doEnt && wid == 0) {
        __threadfence();
        float t = 0.f;
        if (lane < CC)
            t = g_histPart[(plane * 2) * 32 + lane] +
                g_histPart[(plane * 2 + 1) * 32 + lane];
        float msum = t;
#pragma unroll
        for (int o = 16; o > 0; o >>= 1) msum += __shfl_xor_sync(0xffffffffu, msum, o);
        msum += 1e-6f;
        float p = fminf(fmaxf(t / msum, 1e-7f), 1.0f);
        float term = (lane < CC && p > 1e-6f) ? -p * __logf(p + 1e-10f) : 0.f;
#pragma unroll
        for (int o = 16; o > 0; o >>= 1) term += __shfl_xor_sync(0xffffffffu, term, o);
        if (lane == 0) { g_entArr[plane] = term; g_pcount[plane] = 0; }
    }

    // ---- global tail: last block reduces everything ----
    __syncthreads();
    __threadfence();
    if (tid == 0) {
        unsigned int v = atomicAdd(&g_count, 1u);
        s_isLast = (v == (unsigned int)(NBLK - 1));
    }
    __syncthreads();
    if (!s_isLast) return;
    __threadfence();

    float esum = 0.f;
#pragma unroll
    for (int k = 0; k < 4; k++) esum += g_entArr[tid + (k << 7)];   // 512 planes

    float rsum = 0.f, dsum = 0.f;
#pragma unroll
    for (int k = 0; k < 4; k++) {           // warp w handles batches w,w+4,w+8,w+12
        int bb = wid + (k << 2);
        float I = 0.f, U = 0.f, D = 0.f;
#pragma unroll
        for (int r = 0; r < 2; r++) {
            int idx = bb * 64 + lane * 2 + r;
            I += g_blkI[idx];
            U += g_blkU[idx];
            D += g_blkD[idx];
        }
#pragma unroll
        for (int o = 16; o > 0; o >>= 1) {
            I += __shfl_xor_sync(0xffffffffu, I, o);
            U += __shfl_xor_sync(0xffffffffu, U, o);
            D += __shfl_xor_sync(0xffffffffu, D, o);
        }
        rsum += I / (U + 1e-8f);
        dsum += D;
    }
#pragma unroll
    for (int o = 16; o > 0; o >>= 1) esum += __shfl_xor_sync(0xffffffffu, esum, o);

    if (lane == 0) { sE[wid] = esum; sR[wid] = rsum; sD2[wid] = dsum; }
    __syncthreads();
    if (tid == 0) {
        float etot = sE[0] + sE[1] + sE[2] + sE[3];
        float rtot = sR[0] + sR[1] + sR[2] + sR[3];
        float dtot = sD2[0] + sD2[1] + sD2[2] + sD2[3];
        float lu = etot / (512.f + 1e-8f);
        float lb = 1.f - rtot * (1.f / 16.f);
        float ld = dtot * (1.f / ((float)BB * (float)NN));
        out[0] = lu;
        out[1] = lb;
        out[2] = ld;
        out[3] = 0.3f * lu + 0.2f * lb + 0.2f * ld;
        g_count = 0;                        // reset for next graph replay
    }
}

// ---------------------------------------------------------------------------
extern "C" void kernel_launch(void* const* d_in, const int* in_sizes, int n_in,
                              void* d_out, int out_size) {
    const int*   sem   = (const int*)d_in[0];
    const float* masks = (const float*)d_in[1];
    const float* depth = (const float*)d_in[2];
    float* out = (float*)d_out;

    fused_kernel<<<NBLK, TT>>>(sem, masks, depth, out);   // single launch
}

// round 16
// speedup vs baseline: 3.0453x; 1.2971x over previous
#include <cuda_runtime.h>
#include <math.h>

#define BB 16
#define MM 32
#define WW 256
#define NN 65536      // 256*256
#define CC 27
#define T1 256

// ---- scratch (unique writer per element -> no data races) ----
__device__ float g_entArr[BB * MM];   // per-(b,m) entropy
__device__ float g_blkI[BB * MM];     // per-block boundary intersection partial
__device__ float g_blkU[BB * MM];     // per-block boundary union partial
__device__ float g_blkD[BB * MM];     // per-block dbc partial
__device__ unsigned int g_count = 0;  // last-block counter (self-resetting)

// ---------------------------------------------------------------------------
// Fused kernel: 512 blocks (one per (b,m)), 256 threads.  [R3 structure]
//  Part 1: boundary/depth losses on a 2048-px slice (vectorized, in-register
//          neighbors; slice = block & 31 within batch b = block >> 5).
//  Part 2: masked class histogram for the (b,m) plane via per-thread private
//          column-major smem bins (bank = tid%32 -> conflict-free RMW),
//          register butterfly reduce, in-block entropy.
//  Tail  : last finished block combines the 512 partials, writes 4 scalars.
// ---------------------------------------------------------------------------
__global__ __launch_bounds__(T1) void fused_kernel(const int* __restrict__ sem,
                                                   const float* __restrict__ masks,
                                                   const float* __restrict__ depth,
                                                   float* __restrict__ out) {
    __shared__ float s_hist[CC * T1];          // 27,648 B
    __shared__ float s_red[T1 / 32][CC];
    __shared__ float rI[T1 / 32], rU[T1 / 32], rD[T1 / 32];
    __shared__ bool  s_isLast;

    const int block = blockIdx.x;              // b*32 + m
    const int b     = block >> 5;
    const int tid   = threadIdx.x;
    const int lane  = tid & 31;
    const int wid   = tid >> 5;

    float* my = s_hist + tid;                  // bin c at my[c*T1]
#pragma unroll
    for (int c = 0; c < CC; c++) my[c * T1] = 0.f;

    // batch-local vector bases
    const int4*   semv = (const int4*)sem + ((size_t)b << 14);
    const float4* m0v  = (const float4*)(masks + (size_t)b * MM * NN);  // m=0 plane
    const float4* dv   = (const float4*)depth + ((size_t)b << 14);
    const int*    semS = sem + ((size_t)b << 16);
    const float*  m0S  = masks + (size_t)b * MM * NN;
    const float*  dS   = depth + ((size_t)b << 16);

    // ---- Part 1: pixel-loss slice (512 groups of 4 px, 2 per thread) ----
    float inter = 0.f, uni = 0.f, contrib = 0.f;
    const int base_n = (block & 31) << 11;     // slice start within batch
#pragma unroll
    for (int q = 0; q < 2; q++) {
        int n  = base_n + ((q * T1 + tid) << 2);   // first px of group
        int gi = n >> 2;
        int y  = n >> 8, x = n & 255;
        int4   s4  = semv[gi];
        float4 m4  = m0v[gi];
        float4 d4  = dv[gi];
        int giu = (y > 0) ? gi - 64 : gi;          // row above (replicate at y==0)
        int4   s4u = semv[giu];
        float4 m4u = m0v[giu];
        float4 d4u = dv[giu];
        int sl0; float ml0, dl0;
        if (x > 0) { sl0 = semS[n - 1]; ml0 = m0S[n - 1]; dl0 = dS[n - 1]; }
        else       { sl0 = s4.x;        ml0 = m4.x;       dl0 = d4.x; }

        int   s[4]  = {s4.x, s4.y, s4.z, s4.w};
        int   sl[4] = {sl0, s4.x, s4.y, s4.z};
        int   su[4] = {s4u.x, s4u.y, s4u.z, s4u.w};
        float m[4]  = {m4.x, m4.y, m4.z, m4.w};
        float ml[4] = {ml0, m4.x, m4.y, m4.z};
        float mu[4] = {m4u.x, m4u.y, m4u.z, m4u.w};
        float d[4]  = {d4.x, d4.y, d4.z, d4.w};
        float dl[4] = {dl0, d4.x, d4.y, d4.z};
        float du[4] = {d4u.x, d4u.y, d4u.z, d4u.w};
#pragma unroll
        for (int e = 0; e < 4; e++) {
            float semb  = (s[e] != sl[e] || s[e] != su[e]) ? 1.f : 0.f;
            float instb = (fabsf(m[e] - ml[e]) > 0.3f ||
                           fabsf(m[e] - mu[e]) > 0.3f) ? 1.f : 0.f;
            inter += semb * instb;
            uni   += fmaxf(semb, instb);
            float gx = d[e] - dl[e], gy = d[e] - du[e];
            float ss = gx * gx + gy * gy;
            float db = sqrtf(fmaxf(ss, 1e-24f));
            float dbc = fminf(db, 2.f);
            contrib += (1.f + 3.f * dbc) * (1.f - semb) * dbc;
        }
    }
#pragma unroll
    for (int o = 16; o > 0; o >>= 1) {
        inter   += __shfl_down_sync(0xffffffffu, inter,   o);
        uni     += __shfl_down_sync(0xffffffffu, uni,     o);
        contrib += __shfl_down_sync(0xffffffffu, contrib, o);
    }
    if (lane == 0) { rI[wid] = inter; rU[wid] = uni; rD[wid] = contrib; }

    // ---- Part 2: masked histogram (64 groups/thread, 2 per iter) ----
    const float4* mp = (const float4*)masks + (size_t)block * (NN / 4);
#pragma unroll 4
    for (int j = 0; j < 32; j++) {
        int i0 = tid + j * 512;
        float4 v0 = mp[i0];
        float4 v1 = mp[i0 + 256];
        int4   c0 = semv[i0];
        int4   c1 = semv[i0 + 256];
        my[c0.x * T1] += v0.x;
        my[c0.y * T1] += v0.y;
        my[c0.z * T1] += v0.z;
        my[c0.w * T1] += v0.w;
        my[c1.x * T1] += v1.x;
        my[c1.y * T1] += v1.y;
        my[c1.z * T1] += v1.z;
        my[c1.w * T1] += v1.w;
    }
    __syncwarp();

    // pull own column into registers, butterfly-reduce across the warp
    float h[CC];
#pragma unroll
    for (int c = 0; c < CC; c++) h[c] = my[c * T1];
#pragma unroll
    for (int o = 16; o > 0; o >>= 1) {
#pragma unroll
        for (int c = 0; c < CC; c++) h[c] += __shfl_xor_sync(0xffffffffu, h[c], o);
    }
    if (lane == 0) {
#pragma unroll
        for (int c = 0; c < CC; c++) s_red[wid][c] = h[c];
    }
    __syncthreads();

    if (wid == 0) {
        // combine 8 warp partials, entropy over 27 classes
        float t = 0.f;
        if (lane < CC) {
#pragma unroll
            for (int w = 0; w < T1 / 32; w++) t += s_red[w][lane];
        }
        float msum = t;
#pragma unroll
        for (int o = 16; o > 0; o >>= 1) msum += __shfl_xor_sync(0xffffffffu, msum, o);
        msum += 1e-6f;
        float p = t / msum;
        p = fminf(fmaxf(p, 1e-7f), 1.0f);
        float term = (lane < CC && p > 1e-6f) ? -p * __logf(p + 1e-10f) : 0.f;
#pragma unroll
        for (int o = 16; o > 0; o >>= 1) term += __shfl_xor_sync(0xffffffffu, term, o);
        if (lane == 0) g_entArr[block] = term;
    } else if (wid == 1 && lane == 0) {
        float I = 0.f, U = 0.f, D = 0.f;
#pragma unroll
        for (int w = 0; w < T1 / 32; w++) { I += rI[w]; U += rU[w]; D += rD[w]; }
        g_blkI[block] = I;
        g_blkU[block] = U;
        g_blkD[block] = D;
    }

    // ---- Last-block finalize (replaces the separate 4.2us kernel) ----
    __threadfence();
    __syncthreads();
    if (tid == 0) {
        unsigned int v = atomicAdd(&g_count, 1u);
        s_isLast = (v == (unsigned int)(gridDim.x - 1));
    }
    __syncthreads();
    if (!s_isLast) return;
    __threadfence();

    // entropy: 512 entries, 2 per thread
    float e = g_entArr[tid] + g_entArr[tid + 256];
    // per-batch IoU + dbc: warp w handles batches w and w+8 (lane = block in batch)
    float rsum = 0.f, dsum = 0.f;
#pragma unroll
    for (int k = 0; k < 2; k++) {
        int bb = wid + k * 8;
        float I = g_blkI[bb * 32 + lane];
        float U = g_blkU[bb * 32 + lane];
        float D = g_blkD[bb * 32 + lane];
#pragma unroll
        for (int o = 16; o > 0; o >>= 1) {
            I += __shfl_xor_sync(0xffffffffu, I, o);
            U += __shfl_xor_sync(0xffffffffu, U, o);
            D += __shfl_xor_sync(0xffffffffu, D, o);
        }
        rsum += I / (U + 1e-8f);
        dsum += D;
    }
#pragma unroll
    for (int o = 16; o > 0; o >>= 1) e += __shfl_xor_sync(0xffffffffu, e, o);

    __shared__ float sE[8], sR[8], sD2[8];
    if (lane == 0) { sE[wid] = e; sR[wid] = rsum; sD2[wid] = dsum; }
    __syncthreads();
    if (tid == 0) {
        float etot = 0.f, rtot = 0.f, dtot = 0.f;
#pragma unroll
        for (int w = 0; w < 8; w++) { etot += sE[w]; rtot += sR[w]; dtot += sD2[w]; }
        float lu = etot / (512.f + 1e-8f);
        float lb = 1.f - rtot * (1.f / 16.f);
        float ld = dtot * (1.f / ((float)BB * (float)NN));
        out[0] = lu;
        out[1] = lb;
        out[2] = ld;
        out[3] = 0.3f * lu + 0.2f * lb + 0.2f * ld;
        g_count = 0;                           // reset for next graph replay
    }
}

// ---------------------------------------------------------------------------
extern "C" void kernel_launch(void* const* d_in, const int* in_sizes, int n_in,
                              void* d_out, int out_size) {
    const int*   sem   = (const int*)d_in[0];
    const float* masks = (const float*)d_in[1];
    const float* depth = (const float*)d_in[2];
    float* out = (float*)d_out;

    fused_kernel<<<BB * MM, T1>>>(sem, masks, depth, out);   // single launch
}